// round 13
// baseline (speedup 1.0000x reference)
#include <cuda_runtime.h>

#define BATCH 2048
#define NNB   64
#define MM    10
#define FEAT  40
#define RMAX  (MM + 1)
#define RPAD  12
#define PDS   66

typedef unsigned long long ull;

__device__ float g_sig_partial[MM * BATCH];
__device__ unsigned int g_done = 0;

#define EBAR(id)        asm volatile("bar.sync %0, 64;"    :: "r"(id) : "memory")
#define NBAR_SYNC(id)   asm volatile("bar.sync %0, 128;"   :: "r"(id) : "memory")
#define NBAR_ARRIVE(id) asm volatile("bar.arrive %0, 128;" :: "r"(id) : "memory")

__device__ __forceinline__ ull pack2(float lo, float hi) {
    ull r; asm("mov.b64 %0, {%1, %2};" : "=l"(r) : "f"(lo), "f"(hi)); return r;
}
__device__ __forceinline__ void unpack2(ull v, float& lo, float& hi) {
    asm("mov.b64 {%0, %1}, %2;" : "=f"(lo), "=f"(hi) : "l"(v));
}
__device__ __forceinline__ ull fma2(ull a, ull b, ull c) {
    ull r; asm("fma.rn.f32x2 %0, %1, %2, %3;" : "=l"(r) : "l"(a), "l"(b), "l"(c)); return r;
}
__device__ __forceinline__ ull add2(ull a, ull b) {
    ull r; asm("add.rn.f32x2 %0, %1, %2;" : "=l"(r) : "l"(a), "l"(b)); return r;
}
__device__ __forceinline__ ull mul2(ull a, ull b) {
    ull r; asm("mul.rn.f32x2 %0, %1, %2;" : "=l"(r) : "l"(a), "l"(b)); return r;
}

struct __align__(16) ElemSmem {
    float spdA[NNB][PDS];                // raw pairwise dots
    union {
        struct {                          // phase 1: transposed feature staging
            float sxnT[16][NNB];
            float sxb[16];
        } p1;
        struct {                          // phase 2: 3-deep publish ring
            float srow[3][176];           // [0..63] colA, [64..127] colB,
                                          // [128..139] rhsA, [144..155] rhsB, [160] dv2a
        } p2;
    } u;
    float snorm[NNB];
    int   sidx[NNB];
    float red[2][2 * MM + 1];
};

struct BlockSmem {
    ElemSmem e[2];
    float gls[MM], geps[MM];
    int   gcnt[MM];
    int   gmem[MM][MM];
    int   ng;
    unsigned int ticket;
    float sred[4];
};

__global__ void __launch_bounds__(128, 5)
muygps_main(const float* __restrict__ x,
            const float* __restrict__ ls,
            const float* __restrict__ eps,
            const int*   __restrict__ bidx,
            const int*   __restrict__ nidx,
            const float* __restrict__ Y,
            float*       __restrict__ out)
{
    extern __shared__ char smem_raw[];
    BlockSmem* S = reinterpret_cast<BlockSmem*>(smem_raw);
    const int tid = threadIdx.x;
    const int e   = tid >> 6;
    const int i   = tid & 63;
    const int idA = 1 + 2 * e;
    const int idB = 2 + 2 * e;
    const int b   = blockIdx.x * 2 + e;
    ElemSmem* E = &S->e[e];

    if (tid == 0) {
        int ng = 0;
        for (int m = 0; m < MM; m++) {
            float lm = ls[m], em = eps[m];
            int g = -1;
            for (int q = 0; q < ng; q++)
                if (S->gls[q] == lm && S->geps[q] == em) { g = q; break; }
            if (g < 0) { g = ng++; S->gls[g] = lm; S->geps[g] = em; S->gcnt[g] = 0; }
            S->gmem[g][S->gcnt[g]++] = m;
        }
        S->ng = ng;
    }

    const int myidx = nidx[b * NNB + i];
    const float* xrow = x + (size_t)myidx * FEAT;
    const float* xb   = x + (size_t)bidx[b] * FEAT;

    // ---- phase 1: 3 feature tiles (16,16,8); j-packed dots accumulate in spdA
    float nrm = 0.f, cd2 = 0.f;
#pragma unroll
    for (int t = 0; t < 3; t++) {
        const int f0  = (t == 0) ? 0 : (t == 1) ? 16 : 32;
        const int len = (t < 2) ? 16 : 8;
        ull xd[16];
        {
            const ulonglong2* xr = reinterpret_cast<const ulonglong2*>(xrow + f0);
#pragma unroll
            for (int q = 0; q < len / 4; q++) {
                ulonglong2 v = xr[q];
                float f0v, f1v, f2v, f3v;
                unpack2(v.x, f0v, f1v);
                unpack2(v.y, f2v, f3v);
                xd[4*q+0] = pack2(f0v, f0v);
                xd[4*q+1] = pack2(f1v, f1v);
                xd[4*q+2] = pack2(f2v, f2v);
                xd[4*q+3] = pack2(f3v, f3v);
                E->u.p1.sxnT[4*q+0][i] = f0v;
                E->u.p1.sxnT[4*q+1][i] = f1v;
                E->u.p1.sxnT[4*q+2][i] = f2v;
                E->u.p1.sxnT[4*q+3][i] = f3v;
                nrm += f0v*f0v + f1v*f1v;
                nrm += f2v*f2v + f3v*f3v;
            }
        }
        if (i < len) E->u.p1.sxb[i] = xb[f0 + i];
        if (t == 0)  E->sidx[i] = myidx;
        EBAR(idA);

#pragma unroll
        for (int f = 0; f < len; f++) {
            float lo, hi; unpack2(xd[f], lo, hi);
            float d = lo - E->u.p1.sxb[f];
            cd2 += d * d;
        }
        {
            const ulonglong2* colb = reinterpret_cast<const ulonglong2*>(&E->u.p1.sxnT[0][0]);
#pragma unroll 4
            for (int g4 = 0; g4 < 16; g4++) {
                ull acc0 = 0ull, acc1 = 0ull;
#pragma unroll
                for (int f = 0; f < len; f++) {
                    ulonglong2 v = colb[16 * f + g4];
                    acc0 = fma2(xd[f], v.x, acc0);
                    acc1 = fma2(xd[f], v.y, acc1);
                }
                ull* dst = reinterpret_cast<ull*>(&E->spdA[i][4 * g4]);
                if (t == 0) {
                    dst[0] = acc0;
                    dst[1] = acc1;
                } else {
                    dst[0] = add2(dst[0], acc0);
                    dst[1] = add2(dst[1], acc1);
                }
            }
        }
        EBAR(idA);
    }
    E->snorm[i] = nrm;
    const float cdist = (cd2 > 0.f) ? sqrtf(cd2) : 0.f;
    __syncthreads();

    const float* Yrow = Y + ((size_t)b * NNB + i) * MM;
    const int ng = S->ng;

    for (int g = 0; g < ng; g++) {
        const float inv_ls = 1.0f / S->gls[g];
        const float epg    = S->geps[g];
        const int   nm     = S->gcnt[g];

        // ---- packed Kp row from raw dots; TRIANGLE: only packs p <= i/2+1 needed
        ull a2[NNB / 2];
        {
            const float ni = nrm;
            const int pmax = (i >> 1) + 1;
#pragma unroll
            for (int p = 0; p < NNB / 2; p++) {
                if (p > pmax) break;
                ull dot2 = *reinterpret_cast<const ull*>(&E->spdA[i][2 * p]);
                float d0, d1; unpack2(dot2, d0, d1);
                float n0 = E->snorm[2*p], n1 = E->snorm[2*p+1];
                float dd0 = ni + n0 - 2.f * d0;
                float dd1 = ni + n1 - 2.f * d1;
                if (E->sidx[2*p]   == myidx) dd0 = 0.f;
                if (E->sidx[2*p+1] == myidx) dd1 = 0.f;
                dd0 = (dd0 > 0.f) ? sqrtf(dd0) : 0.f;
                dd1 = (dd1 > 0.f) ? sqrtf(dd1) : 0.f;
                float e0 = __expf(-dd0 * inv_ls);
                float e1 = __expf(-dd1 * inv_ls);
                if (2*p   == i) e0 += epg;
                if (2*p+1 == i) e1 += epg;
                a2[p] = pack2(e0, e1);
            }
        }
        const float Kc = __expf(-cdist * inv_ls);

        // ---- packed rhs
        ull rr2[6];
        {
            float rv[RPAD];
#pragma unroll
            for (int r = 0; r < RPAD; r++) rv[r] = 0.f;
#pragma unroll
            for (int r = 0; r < MM; r++)
                if (r < nm) rv[r] = Yrow[S->gmem[g][r]];
#pragma unroll
            for (int r = 0; r < RMAX; r++)
                if (r == nm) rv[r] = Kc;
#pragma unroll
            for (int p = 0; p < 6; p++) rr2[p] = pack2(rv[2*p], rv[2*p+1]);
        }

        float mydv = 0.f;

        // ---- bootstrap: cooperative publish of cols 0/1 into ring buf 0
        {
            float* w0 = E->u.p2.srow[0];
            float lo0, hi0; unpack2(a2[0], lo0, hi0);
            w0[i]      = (i > 0) ? lo0 : 0.f;
            w0[64 + i] = (i > 0) ? hi0 : 0.f;
            if (i == 0) {
                float dv = rsqrtf(lo0);
                mydv = dv;
                w0[160] = dv * dv;
                ulonglong2* wA = reinterpret_cast<ulonglong2*>(w0 + 128);
                wA[0] = make_ulonglong2(rr2[0], rr2[1]);
                wA[1] = make_ulonglong2(rr2[2], rr2[3]);
                wA[2] = make_ulonglong2(rr2[4], rr2[5]);
            }
            if (i == 1) {
                ulonglong2* wB = reinterpret_cast<ulonglong2*>(w0 + 144);
                wB[0] = make_ulonglong2(rr2[0], rr2[1]);
                wB[1] = make_ulonglong2(rr2[2], rr2[3]);
                wB[2] = make_ulonglong2(rr2[4], rr2[5]);
            }
            NBAR_ARRIVE(idA);
        }

        // ---- double-step Cholesky + fused forward solve (rank-2 refactor)
#pragma unroll
        for (int n = 0; n < 32; n++) {
            const int K = 2 * n;
            NBAR_SYNC((n & 1) ? idB : idA);
            const float* rbS = E->u.p2.srow[n % 3];
            float*       wbS = E->u.p2.srow[(n + 1) % 3];

            const float dv2a  = rbS[160];
            const float cak1  = rbS[K + 1];
            const float cbk1  = rbS[64 + K + 1];
            const float cc    = cak1 * dv2a;
            const float diagB = __fmaf_rn(-cc, cak1, cbk1);
            const float sdb   = rsqrtf(diagB);
            const float dv2b  = sdb * sdb;
            float aKlo, aKhi; unpack2(a2[n], aKlo, aKhi);
            const float t1  = aKlo * dv2a;
            const float t2  = __fmaf_rn(-t1, cak1, aKhi) * dv2b;
            const float t1p = __fmaf_rn(-t2, cc, t1);    // rank-2 combined multiplier
            const ull nt1p2 = pack2(-t1p, -t1p);
            const ull nt22  = pack2(-t2,  -t2);

            if (n < 31) {
                const int cp2 = n + 1;
                float sA = 0.f, sB = 0.f;
                if (i > K + 1) {
                    ull vA = *reinterpret_cast<const ull*>(rbS + 2 * cp2);
                    ull vB = *reinterpret_cast<const ull*>(rbS + 64 + 2 * cp2);
                    a2[cp2] = fma2(nt1p2, vA, a2[cp2]);
                    a2[cp2] = fma2(nt22,  vB, a2[cp2]);
                    if (i > K + 2) unpack2(a2[cp2], sA, sB);
                }
                wbS[i]      = sA;
                wbS[64 + i] = sB;
                if (i == K + 2) {
                    float dlo, dhi_; unpack2(a2[cp2], dlo, dhi_);
                    float dv = rsqrtf(dlo);
                    mydv = dv;
                    wbS[160] = dv * dv;
                }
                // pivots' rhs BEFORE publish+arrive (needed next interval)
                if (i == K + 2 || i == K + 3) {
                    const ulonglong2* rA = reinterpret_cast<const ulonglong2*>(rbS + 128);
                    const ulonglong2* rB = reinterpret_cast<const ulonglong2*>(rbS + 144);
#pragma unroll
                    for (int c = 0; c < 3; c++) {
                        ulonglong2 vA = rA[c], vB = rB[c];
                        rr2[2*c]   = fma2(nt1p2, vA.x, rr2[2*c]);
                        rr2[2*c]   = fma2(nt22,  vB.x, rr2[2*c]);
                        rr2[2*c+1] = fma2(nt1p2, vA.y, rr2[2*c+1]);
                        rr2[2*c+1] = fma2(nt22,  vB.y, rr2[2*c+1]);
                    }
                    if (i == K + 2) {
                        ulonglong2* wA = reinterpret_cast<ulonglong2*>(wbS + 128);
                        wA[0] = make_ulonglong2(rr2[0], rr2[1]);
                        wA[1] = make_ulonglong2(rr2[2], rr2[3]);
                        wA[2] = make_ulonglong2(rr2[4], rr2[5]);
                    } else {
                        ulonglong2* wB = reinterpret_cast<ulonglong2*>(wbS + 144);
                        wB[0] = make_ulonglong2(rr2[0], rr2[1]);
                        wB[1] = make_ulonglong2(rr2[2], rr2[3]);
                        wB[2] = make_ulonglong2(rr2[4], rr2[5]);
                    }
                }
                NBAR_ARRIVE((n & 1) ? idA : idB);

                // ---- off-chain: remaining rhs + triangle-bounded tail
                if (i == K + 1) {
                    mydv = sdb;
                    const ull nt12 = pack2(-t1, -t1);
                    const ulonglong2* rA = reinterpret_cast<const ulonglong2*>(rbS + 128);
#pragma unroll
                    for (int c = 0; c < 3; c++) {
                        ulonglong2 v = rA[c];
                        rr2[2*c]   = fma2(nt12, v.x, rr2[2*c]);
                        rr2[2*c+1] = fma2(nt12, v.y, rr2[2*c+1]);
                    }
                } else if (i > K + 3) {
                    const ulonglong2* rA = reinterpret_cast<const ulonglong2*>(rbS + 128);
                    const ulonglong2* rB = reinterpret_cast<const ulonglong2*>(rbS + 144);
#pragma unroll
                    for (int c = 0; c < 3; c++) {
                        ulonglong2 vA = rA[c], vB = rB[c];
                        rr2[2*c]   = fma2(nt1p2, vA.x, rr2[2*c]);
                        rr2[2*c]   = fma2(nt22,  vB.x, rr2[2*c]);
                        rr2[2*c+1] = fma2(nt1p2, vA.y, rr2[2*c+1]);
                        rr2[2*c+1] = fma2(nt22,  vB.y, rr2[2*c+1]);
                    }
                }
                if (i > K + 1) {
                    const int pt0 = n + 2;
                    if (pt0 & 1) {
                        if (pt0 < 32 && (pt0 << 1) <= i) {
                            ull vA = *reinterpret_cast<const ull*>(rbS + 2 * pt0);
                            ull vB = *reinterpret_cast<const ull*>(rbS + 64 + 2 * pt0);
                            a2[pt0] = fma2(nt1p2, vA, a2[pt0]);
                            a2[pt0] = fma2(nt22,  vB, a2[pt0]);
                        }
                    }
                    const int c0 = (pt0 + 1) >> 1;
#pragma unroll
                    for (int c = c0; c < 16; c++) {
                        if (4 * c > i) break;            // triangle: cols > i are dead
                        ulonglong2 vA2 = *reinterpret_cast<const ulonglong2*>(rbS + 4 * c);
                        ulonglong2 vB2 = *reinterpret_cast<const ulonglong2*>(rbS + 64 + 4 * c);
                        a2[2*c]   = fma2(nt1p2, vA2.x, a2[2*c]);
                        a2[2*c]   = fma2(nt22,  vB2.x, a2[2*c]);
                        a2[2*c+1] = fma2(nt1p2, vA2.y, a2[2*c+1]);
                        a2[2*c+1] = fma2(nt22,  vB2.y, a2[2*c+1]);
                    }
                }
            } else {
                // last interval: only thread 63 (== K+1) has rhs work
                if (i == K + 1) {
                    mydv = sdb;
                    const ull nt12 = pack2(-t1, -t1);
                    const ulonglong2* rA = reinterpret_cast<const ulonglong2*>(rbS + 128);
#pragma unroll
                    for (int c = 0; c < 3; c++) {
                        ulonglong2 v = rA[c];
                        rr2[2*c]   = fma2(nt12, v.x, rr2[2*c]);
                        rr2[2*c+1] = fma2(nt12, v.y, rr2[2*c+1]);
                    }
                }
            }
        }

        // ---- zs = D^{-1/2} L^{-1} rhs; outputs are inner products
        {
            ull mv2 = pack2(mydv, mydv);
#pragma unroll
            for (int p = 0; p < 6; p++) rr2[p] = mul2(rr2[p], mv2);
        }
        float z[RPAD];
#pragma unroll
        for (int p = 0; p < 6; p++) unpack2(rr2[p], z[2*p], z[2*p+1]);

        float zKc = 0.f;
#pragma unroll
        for (int r = 0; r < RMAX; r++)
            if (r == nm) zKc = z[r];

        float pm[MM], sg[MM];
#pragma unroll
        for (int r = 0; r < MM; r++) { pm[r] = z[r] * zKc; sg[r] = z[r] * z[r]; }
        float vv = zKc * zKc;

#pragma unroll
        for (int off = 16; off > 0; off >>= 1) {
#pragma unroll
            for (int r = 0; r < MM; r++) {
                pm[r] += __shfl_xor_sync(0xffffffffu, pm[r], off);
                sg[r] += __shfl_xor_sync(0xffffffffu, sg[r], off);
            }
            vv += __shfl_xor_sync(0xffffffffu, vv, off);
        }
        {
            const int w = (tid >> 5) & 1, lane = tid & 31;
            if (lane == 0) {
#pragma unroll
                for (int r = 0; r < MM; r++) {
                    E->red[w][r]      = pm[r];
                    E->red[w][MM + r] = sg[r];
                }
                E->red[w][2 * MM] = vv;
            }
        }
        EBAR(idA);
        if (i == 0) {
            float var = 1.0f - (E->red[0][2*MM] + E->red[1][2*MM]);
            for (int r = 0; r < nm; r++) {
                int m = S->gmem[g][r];
                out[b * MM + m]              = E->red[0][r] + E->red[1][r];
                out[BATCH * MM + b * MM + m] = var;
                g_sig_partial[m * BATCH + b] = E->red[0][MM+r] + E->red[1][MM+r];
            }
        }
        EBAR(idA);
    }

    // ---- last-block sigma reduction (deterministic fixed-order sum)
    __threadfence();
    __syncthreads();
    if (tid == 0) S->ticket = atomicAdd(&g_done, 1u);
    __syncthreads();
    if (S->ticket == gridDim.x - 1) {
        __threadfence();
        const int lane = tid & 31, w = tid >> 5;
        for (int m = 0; m < MM; m++) {
            float s = 0.f;
            for (int t = tid; t < BATCH; t += 128)
                s += g_sig_partial[m * BATCH + t];
#pragma unroll
            for (int off = 16; off > 0; off >>= 1)
                s += __shfl_down_sync(0xffffffffu, s, off);
            if (lane == 0) S->sred[w] = s;
            __syncthreads();
            if (tid == 0) {
                float tot = S->sred[0] + S->sred[1] + S->sred[2] + S->sred[3];
                out[2 * BATCH * MM + m] = tot / (float)(BATCH * NNB);
            }
            __syncthreads();
        }
        if (tid == 0) g_done = 0;
    }
}

extern "C" void kernel_launch(void* const* d_in, const int* in_sizes, int n_in,
                              void* d_out, int out_size)
{
    const float* x    = (const float*)d_in[0];
    const float* ls   = (const float*)d_in[1];
    const float* eps  = (const float*)d_in[2];
    const int*   bidx = (const int*)d_in[3];
    const int*   nidx = (const int*)d_in[4];
    const float* Y    = (const float*)d_in[5];
    float* out = (float*)d_out;

    cudaFuncSetAttribute(muygps_main, cudaFuncAttributeMaxDynamicSharedMemorySize,
                         (int)sizeof(BlockSmem));
    muygps_main<<<BATCH / 2, 128, sizeof(BlockSmem)>>>(x, ls, eps, bidx, nidx, Y, out);
}

// round 14
// speedup vs baseline: 1.1687x; 1.1687x over previous
#include <cuda_runtime.h>

#define BATCH 2048
#define NNB   64
#define MM    10
#define FEAT  40
#define RMAX  (MM + 1)
#define RPAD  12
#define PDS   66

typedef unsigned long long ull;

__device__ float g_sig_partial[MM * BATCH];
__device__ unsigned int g_done = 0;

#define EBAR(id)        asm volatile("bar.sync %0, 64;"    :: "r"(id) : "memory")
#define NBAR_SYNC(id)   asm volatile("bar.sync %0, 128;"   :: "r"(id) : "memory")
#define NBAR_ARRIVE(id) asm volatile("bar.arrive %0, 128;" :: "r"(id) : "memory")

__device__ __forceinline__ ull pack2(float lo, float hi) {
    ull r; asm("mov.b64 %0, {%1, %2};" : "=l"(r) : "f"(lo), "f"(hi)); return r;
}
__device__ __forceinline__ void unpack2(ull v, float& lo, float& hi) {
    asm("mov.b64 {%0, %1}, %2;" : "=f"(lo), "=f"(hi) : "l"(v));
}
__device__ __forceinline__ ull fma2(ull a, ull b, ull c) {
    ull r; asm("fma.rn.f32x2 %0, %1, %2, %3;" : "=l"(r) : "l"(a), "l"(b), "l"(c)); return r;
}
__device__ __forceinline__ ull add2(ull a, ull b) {
    ull r; asm("add.rn.f32x2 %0, %1, %2;" : "=l"(r) : "l"(a), "l"(b)); return r;
}
__device__ __forceinline__ ull mul2(ull a, ull b) {
    ull r; asm("mul.rn.f32x2 %0, %1, %2;" : "=l"(r) : "l"(a), "l"(b)); return r;
}

struct __align__(16) ElemSmem {
    float spdA[NNB][PDS];                // raw pairwise dots
    union {
        struct {                          // phase 1: transposed feature staging
            float sxnT[16][NNB];
            float sxb[16];
        } p1;
        struct {                          // phase 2: 3-deep publish ring
            float srow[3][176];           // [0..63] colA, [64..127] colB,
                                          // [128..139] rhsA, [144..155] rhsB, [160] dv2a
        } p2;
    } u;
    float snorm[NNB];
    int   sidx[NNB];
    float red[2][2 * MM + 1];
};

struct BlockSmem {
    ElemSmem e[2];
    float gls[MM], geps[MM];
    int   gcnt[MM];
    int   gmem[MM][MM];
    int   ng;
    unsigned int ticket;
    float sred[4];
};

__global__ void __launch_bounds__(128, 5)
muygps_main(const float* __restrict__ x,
            const float* __restrict__ ls,
            const float* __restrict__ eps,
            const int*   __restrict__ bidx,
            const int*   __restrict__ nidx,
            const float* __restrict__ Y,
            float*       __restrict__ out)
{
    extern __shared__ char smem_raw[];
    BlockSmem* S = reinterpret_cast<BlockSmem*>(smem_raw);
    const int tid = threadIdx.x;
    const int e   = tid >> 6;
    const int i   = tid & 63;
    const int idA = 1 + 2 * e;
    const int idB = 2 + 2 * e;
    const int b   = blockIdx.x * 2 + e;
    ElemSmem* E = &S->e[e];
    const bool hiwarp = (i & 32) != 0;   // warp-uniform triangle predicate

    if (tid == 0) {
        int ng = 0;
        for (int m = 0; m < MM; m++) {
            float lm = ls[m], em = eps[m];
            int g = -1;
            for (int q = 0; q < ng; q++)
                if (S->gls[q] == lm && S->geps[q] == em) { g = q; break; }
            if (g < 0) { g = ng++; S->gls[g] = lm; S->geps[g] = em; S->gcnt[g] = 0; }
            S->gmem[g][S->gcnt[g]++] = m;
        }
        S->ng = ng;
    }

    const int myidx = nidx[b * NNB + i];
    const float* xrow = x + (size_t)myidx * FEAT;
    const float* xb   = x + (size_t)bidx[b] * FEAT;

    // ---- phase 1: 3 feature tiles (16,16,8); j-packed dots accumulate in spdA
    float nrm = 0.f, cd2 = 0.f;
#pragma unroll
    for (int t = 0; t < 3; t++) {
        const int f0  = (t == 0) ? 0 : (t == 1) ? 16 : 32;
        const int len = (t < 2) ? 16 : 8;
        ull xd[16];
        {
            const ulonglong2* xr = reinterpret_cast<const ulonglong2*>(xrow + f0);
#pragma unroll
            for (int q = 0; q < len / 4; q++) {
                ulonglong2 v = xr[q];
                float f0v, f1v, f2v, f3v;
                unpack2(v.x, f0v, f1v);
                unpack2(v.y, f2v, f3v);
                xd[4*q+0] = pack2(f0v, f0v);
                xd[4*q+1] = pack2(f1v, f1v);
                xd[4*q+2] = pack2(f2v, f2v);
                xd[4*q+3] = pack2(f3v, f3v);
                E->u.p1.sxnT[4*q+0][i] = f0v;
                E->u.p1.sxnT[4*q+1][i] = f1v;
                E->u.p1.sxnT[4*q+2][i] = f2v;
                E->u.p1.sxnT[4*q+3][i] = f3v;
                nrm += f0v*f0v + f1v*f1v;
                nrm += f2v*f2v + f3v*f3v;
            }
        }
        if (i < len) E->u.p1.sxb[i] = xb[f0 + i];
        if (t == 0)  E->sidx[i] = myidx;
        EBAR(idA);

#pragma unroll
        for (int f = 0; f < len; f++) {
            float lo, hi; unpack2(xd[f], lo, hi);
            float d = lo - E->u.p1.sxb[f];
            cd2 += d * d;
        }
        {
            const ulonglong2* colb = reinterpret_cast<const ulonglong2*>(&E->u.p1.sxnT[0][0]);
#pragma unroll 4
            for (int g4 = 0; g4 < 16; g4++) {
                ull acc0 = 0ull, acc1 = 0ull;
#pragma unroll
                for (int f = 0; f < len; f++) {
                    ulonglong2 v = colb[16 * f + g4];
                    acc0 = fma2(xd[f], v.x, acc0);
                    acc1 = fma2(xd[f], v.y, acc1);
                }
                ull* dst = reinterpret_cast<ull*>(&E->spdA[i][4 * g4]);
                if (t == 0) {
                    dst[0] = acc0;
                    dst[1] = acc1;
                } else {
                    dst[0] = add2(dst[0], acc0);
                    dst[1] = add2(dst[1], acc1);
                }
            }
        }
        EBAR(idA);
    }
    E->snorm[i] = nrm;
    const float cdist = (cd2 > 0.f) ? sqrtf(cd2) : 0.f;
    __syncthreads();

    const float* Yrow = Y + ((size_t)b * NNB + i) * MM;
    const int ng = S->ng;

    for (int g = 0; g < ng; g++) {
        const float inv_ls = 1.0f / S->gls[g];
        const float epg    = S->geps[g];
        const int   nm     = S->gcnt[g];

        // ---- packed Kp row from raw dots; warp-uniform triangle:
        //      low warp (i<32) never reads packs >= 17
        ull a2[NNB / 2];
        {
            const float ni = nrm;
#pragma unroll
            for (int p = 0; p < 17; p++) {
                ull dot2 = *reinterpret_cast<const ull*>(&E->spdA[i][2 * p]);
                float d0, d1; unpack2(dot2, d0, d1);
                float dd0 = ni + E->snorm[2*p]   - 2.f * d0;
                float dd1 = ni + E->snorm[2*p+1] - 2.f * d1;
                if (E->sidx[2*p]   == myidx) dd0 = 0.f;
                if (E->sidx[2*p+1] == myidx) dd1 = 0.f;
                dd0 = (dd0 > 0.f) ? sqrtf(dd0) : 0.f;
                dd1 = (dd1 > 0.f) ? sqrtf(dd1) : 0.f;
                float e0 = __expf(-dd0 * inv_ls);
                float e1 = __expf(-dd1 * inv_ls);
                if (2*p   == i) e0 += epg;
                if (2*p+1 == i) e1 += epg;
                a2[p] = pack2(e0, e1);
            }
            if (hiwarp) {
#pragma unroll
                for (int p = 17; p < NNB / 2; p++) {
                    ull dot2 = *reinterpret_cast<const ull*>(&E->spdA[i][2 * p]);
                    float d0, d1; unpack2(dot2, d0, d1);
                    float dd0 = ni + E->snorm[2*p]   - 2.f * d0;
                    float dd1 = ni + E->snorm[2*p+1] - 2.f * d1;
                    if (E->sidx[2*p]   == myidx) dd0 = 0.f;
                    if (E->sidx[2*p+1] == myidx) dd1 = 0.f;
                    dd0 = (dd0 > 0.f) ? sqrtf(dd0) : 0.f;
                    dd1 = (dd1 > 0.f) ? sqrtf(dd1) : 0.f;
                    float e0 = __expf(-dd0 * inv_ls);
                    float e1 = __expf(-dd1 * inv_ls);
                    if (2*p   == i) e0 += epg;
                    if (2*p+1 == i) e1 += epg;
                    a2[p] = pack2(e0, e1);
                }
            }
        }
        const float Kc = __expf(-cdist * inv_ls);

        // ---- packed rhs
        ull rr2[6];
        {
            float rv[RPAD];
#pragma unroll
            for (int r = 0; r < RPAD; r++) rv[r] = 0.f;
#pragma unroll
            for (int r = 0; r < MM; r++)
                if (r < nm) rv[r] = Yrow[S->gmem[g][r]];
#pragma unroll
            for (int r = 0; r < RMAX; r++)
                if (r == nm) rv[r] = Kc;
#pragma unroll
            for (int p = 0; p < 6; p++) rr2[p] = pack2(rv[2*p], rv[2*p+1]);
        }

        float mydv = 0.f;

        // ---- bootstrap: cooperative publish of cols 0/1 into ring buf 0
        {
            float* w0 = E->u.p2.srow[0];
            float lo0, hi0; unpack2(a2[0], lo0, hi0);
            w0[i]      = (i > 0) ? lo0 : 0.f;
            w0[64 + i] = (i > 0) ? hi0 : 0.f;
            if (i == 0) {
                float dv = rsqrtf(lo0);
                mydv = dv;
                w0[160] = dv * dv;
                ulonglong2* wA = reinterpret_cast<ulonglong2*>(w0 + 128);
                wA[0] = make_ulonglong2(rr2[0], rr2[1]);
                wA[1] = make_ulonglong2(rr2[2], rr2[3]);
                wA[2] = make_ulonglong2(rr2[4], rr2[5]);
            }
            if (i == 1) {
                ulonglong2* wB = reinterpret_cast<ulonglong2*>(w0 + 144);
                wB[0] = make_ulonglong2(rr2[0], rr2[1]);
                wB[1] = make_ulonglong2(rr2[2], rr2[3]);
                wB[2] = make_ulonglong2(rr2[4], rr2[5]);
            }
            NBAR_ARRIVE(idA);
        }

        // ---- double-step Cholesky + fused forward solve (rank-2 fold)
#pragma unroll
        for (int n = 0; n < 32; n++) {
            const int K = 2 * n;
            NBAR_SYNC((n & 1) ? idB : idA);
            const float* rbS = E->u.p2.srow[n % 3];
            float*       wbS = E->u.p2.srow[(n + 1) % 3];

            const float dv2a  = rbS[160];
            const float cak1  = rbS[K + 1];
            const float cbk1  = rbS[64 + K + 1];
            const float cc    = cak1 * dv2a;
            const float diagB = __fmaf_rn(-cc, cak1, cbk1);
            const float sdb   = rsqrtf(diagB);
            const float dv2b  = sdb * sdb;
            float aKlo, aKhi; unpack2(a2[n], aKlo, aKhi);
            const float t1  = aKlo * dv2a;
            const float t2  = __fmaf_rn(-t1, cak1, aKhi) * dv2b;
            const float t1p = __fmaf_rn(-t2, cc, t1);   // rank-2 combined multiplier
            const ull nt1p2 = pack2(-t1p, -t1p);
            const ull nt22  = pack2(-t2,  -t2);

            if (n < 31) {
                const int cp2 = n + 1;              // pack holding cols K+2,K+3
                float sA = 0.f, sB = 0.f;
                if (i > K + 1) {
                    ull vA = *reinterpret_cast<const ull*>(rbS + 2 * cp2);
                    ull vB = *reinterpret_cast<const ull*>(rbS + 64 + 2 * cp2);
                    a2[cp2] = fma2(nt1p2, vA, a2[cp2]);
                    a2[cp2] = fma2(nt22,  vB, a2[cp2]);
                    if (i > K + 2) unpack2(a2[cp2], sA, sB);
                }
                wbS[i]      = sA;
                wbS[64 + i] = sB;
                if (i == K + 2) {
                    float dlo, dhi_; unpack2(a2[cp2], dlo, dhi_);
                    float dv = rsqrtf(dlo);
                    mydv = dv;
                    wbS[160] = dv * dv;
                }
            }

            // rhs elimination (R12 placement)
            if (i == K + 1) {
                mydv = sdb;
                const ull nt12 = pack2(-t1, -t1);
                const ulonglong2* rA = reinterpret_cast<const ulonglong2*>(rbS + 128);
#pragma unroll
                for (int c = 0; c < 3; c++) {
                    ulonglong2 v = rA[c];
                    rr2[2*c]   = fma2(nt12, v.x, rr2[2*c]);
                    rr2[2*c+1] = fma2(nt12, v.y, rr2[2*c+1]);
                }
            } else if (i > K + 1) {
                const ulonglong2* rA = reinterpret_cast<const ulonglong2*>(rbS + 128);
                const ulonglong2* rB = reinterpret_cast<const ulonglong2*>(rbS + 144);
#pragma unroll
                for (int c = 0; c < 3; c++) {
                    ulonglong2 vA = rA[c], vB = rB[c];
                    rr2[2*c]   = fma2(nt1p2, vA.x, rr2[2*c]);
                    rr2[2*c]   = fma2(nt22,  vB.x, rr2[2*c]);
                    rr2[2*c+1] = fma2(nt1p2, vA.y, rr2[2*c+1]);
                    rr2[2*c+1] = fma2(nt22,  vB.y, rr2[2*c+1]);
                }
            }

            if (n < 31) {
                if (i == K + 2) {
                    ulonglong2* wA = reinterpret_cast<ulonglong2*>(wbS + 128);
                    wA[0] = make_ulonglong2(rr2[0], rr2[1]);
                    wA[1] = make_ulonglong2(rr2[2], rr2[3]);
                    wA[2] = make_ulonglong2(rr2[4], rr2[5]);
                }
                if (i == K + 3) {
                    ulonglong2* wB = reinterpret_cast<ulonglong2*>(wbS + 144);
                    wB[0] = make_ulonglong2(rr2[0], rr2[1]);
                    wB[1] = make_ulonglong2(rr2[2], rr2[3]);
                    wB[2] = make_ulonglong2(rr2[4], rr2[5]);
                }
                NBAR_ARRIVE((n & 1) ? idA : idB);

                // ---- tail: remaining packs; warp-uniform triangle split
                if (i > K + 1) {
                    const int pt0 = n + 2;           // first tail pack
                    if (pt0 & 1) {
                        if (pt0 <= 16) {
                            ull vA = *reinterpret_cast<const ull*>(rbS + 2 * pt0);
                            ull vB = *reinterpret_cast<const ull*>(rbS + 64 + 2 * pt0);
                            a2[pt0] = fma2(nt1p2, vA, a2[pt0]);
                            a2[pt0] = fma2(nt22,  vB, a2[pt0]);
                        } else if (pt0 < 32 && hiwarp) {
                            ull vA = *reinterpret_cast<const ull*>(rbS + 2 * pt0);
                            ull vB = *reinterpret_cast<const ull*>(rbS + 64 + 2 * pt0);
                            a2[pt0] = fma2(nt1p2, vA, a2[pt0]);
                            a2[pt0] = fma2(nt22,  vB, a2[pt0]);
                        }
                    }
                    const int c0 = (pt0 + 1) >> 1;
#pragma unroll
                    for (int c = c0; c < 8; c++) {
                        ulonglong2 vA2 = *reinterpret_cast<const ulonglong2*>(rbS + 4 * c);
                        ulonglong2 vB2 = *reinterpret_cast<const ulonglong2*>(rbS + 64 + 4 * c);
                        a2[2*c]   = fma2(nt1p2, vA2.x, a2[2*c]);
                        a2[2*c]   = fma2(nt22,  vB2.x, a2[2*c]);
                        a2[2*c+1] = fma2(nt1p2, vA2.y, a2[2*c+1]);
                        a2[2*c+1] = fma2(nt22,  vB2.y, a2[2*c+1]);
                    }
                    if (hiwarp) {
                        const int ch0 = (c0 > 8) ? c0 : 8;
#pragma unroll
                        for (int c = ch0; c < 16; c++) {
                            ulonglong2 vA2 = *reinterpret_cast<const ulonglong2*>(rbS + 4 * c);
                            ulonglong2 vB2 = *reinterpret_cast<const ulonglong2*>(rbS + 64 + 4 * c);
                            a2[2*c]   = fma2(nt1p2, vA2.x, a2[2*c]);
                            a2[2*c]   = fma2(nt22,  vB2.x, a2[2*c]);
                            a2[2*c+1] = fma2(nt1p2, vA2.y, a2[2*c+1]);
                            a2[2*c+1] = fma2(nt22,  vB2.y, a2[2*c+1]);
                        }
                    }
                }
            }
        }

        // ---- zs = D^{-1/2} L^{-1} rhs; outputs are inner products
        {
            ull mv2 = pack2(mydv, mydv);
#pragma unroll
            for (int p = 0; p < 6; p++) rr2[p] = mul2(rr2[p], mv2);
        }
        float z[RPAD];
#pragma unroll
        for (int p = 0; p < 6; p++) unpack2(rr2[p], z[2*p], z[2*p+1]);

        float zKc = 0.f;
#pragma unroll
        for (int r = 0; r < RMAX; r++)
            if (r == nm) zKc = z[r];

        float pm[MM], sg[MM];
#pragma unroll
        for (int r = 0; r < MM; r++) { pm[r] = z[r] * zKc; sg[r] = z[r] * z[r]; }
        float vv = zKc * zKc;

#pragma unroll
        for (int off = 16; off > 0; off >>= 1) {
#pragma unroll
            for (int r = 0; r < MM; r++) {
                pm[r] += __shfl_xor_sync(0xffffffffu, pm[r], off);
                sg[r] += __shfl_xor_sync(0xffffffffu, sg[r], off);
            }
            vv += __shfl_xor_sync(0xffffffffu, vv, off);
        }
        {
            const int w = (tid >> 5) & 1, lane = tid & 31;
            if (lane == 0) {
#pragma unroll
                for (int r = 0; r < MM; r++) {
                    E->red[w][r]      = pm[r];
                    E->red[w][MM + r] = sg[r];
                }
                E->red[w][2 * MM] = vv;
            }
        }
        EBAR(idA);
        if (i == 0) {
            float var = 1.0f - (E->red[0][2*MM] + E->red[1][2*MM]);
            for (int r = 0; r < nm; r++) {
                int m = S->gmem[g][r];
                out[b * MM + m]              = E->red[0][r] + E->red[1][r];
                out[BATCH * MM + b * MM + m] = var;
                g_sig_partial[m * BATCH + b] = E->red[0][MM+r] + E->red[1][MM+r];
            }
        }
        EBAR(idA);
    }

    // ---- last-block sigma reduction (deterministic fixed-order sum)
    __threadfence();
    __syncthreads();
    if (tid == 0) S->ticket = atomicAdd(&g_done, 1u);
    __syncthreads();
    if (S->ticket == gridDim.x - 1) {
        __threadfence();
        const int lane = tid & 31, w = tid >> 5;
        for (int m = 0; m < MM; m++) {
            float s = 0.f;
            for (int t = tid; t < BATCH; t += 128)
                s += g_sig_partial[m * BATCH + t];
#pragma unroll
            for (int off = 16; off > 0; off >>= 1)
                s += __shfl_down_sync(0xffffffffu, s, off);
            if (lane == 0) S->sred[w] = s;
            __syncthreads();
            if (tid == 0) {
                float tot = S->sred[0] + S->sred[1] + S->sred[2] + S->sred[3];
                out[2 * BATCH * MM + m] = tot / (float)(BATCH * NNB);
            }
            __syncthreads();
        }
        if (tid == 0) g_done = 0;
    }
}

extern "C" void kernel_launch(void* const* d_in, const int* in_sizes, int n_in,
                              void* d_out, int out_size)
{
    const float* x    = (const float*)d_in[0];
    const float* ls   = (const float*)d_in[1];
    const float* eps  = (const float*)d_in[2];
    const int*   bidx = (const int*)d_in[3];
    const int*   nidx = (const int*)d_in[4];
    const float* Y    = (const float*)d_in[5];
    float* out = (float*)d_out;

    cudaFuncSetAttribute(muygps_main, cudaFuncAttributeMaxDynamicSharedMemorySize,
                         (int)sizeof(BlockSmem));
    muygps_main<<<BATCH / 2, 128, sizeof(BlockSmem)>>>(x, ls, eps, bidx, nidx, Y, out);
}

// round 15
// speedup vs baseline: 1.2268x; 1.0497x over previous
#include <cuda_runtime.h>

#define BATCH 2048
#define NNB   64
#define MM    10
#define FEAT  40
#define RMAX  (MM + 1)
#define RPAD  12
#define PDS   66

typedef unsigned long long ull;

__device__ float g_sig_partial[MM * BATCH];
__device__ unsigned int g_done = 0;

#define EBAR(id)        asm volatile("bar.sync %0, 64;"    :: "r"(id) : "memory")
#define NBAR_SYNC(id)   asm volatile("bar.sync %0, 128;"   :: "r"(id) : "memory")
#define NBAR_ARRIVE(id) asm volatile("bar.arrive %0, 128;" :: "r"(id) : "memory")

__device__ __forceinline__ ull pack2(float lo, float hi) {
    ull r; asm("mov.b64 %0, {%1, %2};" : "=l"(r) : "f"(lo), "f"(hi)); return r;
}
__device__ __forceinline__ void unpack2(ull v, float& lo, float& hi) {
    asm("mov.b64 {%0, %1}, %2;" : "=f"(lo), "=f"(hi) : "l"(v));
}
__device__ __forceinline__ ull fma2(ull a, ull b, ull c) {
    ull r; asm("fma.rn.f32x2 %0, %1, %2, %3;" : "=l"(r) : "l"(a), "l"(b), "l"(c)); return r;
}
__device__ __forceinline__ ull add2(ull a, ull b) {
    ull r; asm("add.rn.f32x2 %0, %1, %2;" : "=l"(r) : "l"(a), "l"(b)); return r;
}
__device__ __forceinline__ ull mul2(ull a, ull b) {
    ull r; asm("mul.rn.f32x2 %0, %1, %2;" : "=l"(r) : "l"(a), "l"(b)); return r;
}

struct __align__(16) ElemSmem {
    float spdA[NNB][PDS];                // raw pairwise dots
    union {
        struct {                          // phase 1: transposed feature staging
            float sxnT[16][NNB];
            float sxb[16];
        } p1;
        struct {                          // phase 2: 3-deep publish ring
            float srow[3][176];           // [0..63] colA, [64..127] colB,
                                          // [128..139] rhsA, [144..155] rhsB, [160] dv2a
        } p2;
    } u;
    float snorm[NNB];
    int   sidx[NNB];
    float red[2][2 * MM + 1];
};

struct BlockSmem {
    ElemSmem e[2];
    float gls[MM], geps[MM];
    int   gcnt[MM];
    int   gmem[MM][MM];
    int   ng;
    unsigned int ticket;
    float sred[4];
};

// one g4 group of the j-packed Gram update
#define GRAM_G4(g4)                                                              \
    {                                                                            \
        ull acc0 = 0ull, acc1 = 0ull;                                            \
        _Pragma("unroll")                                                        \
        for (int f = 0; f < len; f++) {                                          \
            ulonglong2 v = colb[16 * f + (g4)];                                  \
            acc0 = fma2(xd[f], v.x, acc0);                                       \
            acc1 = fma2(xd[f], v.y, acc1);                                       \
        }                                                                        \
        ull* dst = reinterpret_cast<ull*>(&E->spdA[i][4 * (g4)]);                \
        if (t == 0) { dst[0] = acc0; dst[1] = acc1; }                            \
        else        { dst[0] = add2(dst[0], acc0); dst[1] = add2(dst[1], acc1); }\
    }

__global__ void __launch_bounds__(128, 5)
muygps_main(const float* __restrict__ x,
            const float* __restrict__ ls,
            const float* __restrict__ eps,
            const int*   __restrict__ bidx,
            const int*   __restrict__ nidx,
            const float* __restrict__ Y,
            float*       __restrict__ out)
{
    extern __shared__ char smem_raw[];
    BlockSmem* S = reinterpret_cast<BlockSmem*>(smem_raw);
    const int tid = threadIdx.x;
    const int e   = tid >> 6;
    const int i   = tid & 63;
    const int idA = 1 + 2 * e;
    const int idB = 2 + 2 * e;
    const int b   = blockIdx.x * 2 + e;
    ElemSmem* E = &S->e[e];
    const bool hiwarp = (i & 32) != 0;   // warp-uniform triangle predicate

    if (tid == 0) {
        int ng = 0;
        for (int m = 0; m < MM; m++) {
            float lm = ls[m], em = eps[m];
            int g = -1;
            for (int q = 0; q < ng; q++)
                if (S->gls[q] == lm && S->geps[q] == em) { g = q; break; }
            if (g < 0) { g = ng++; S->gls[g] = lm; S->geps[g] = em; S->gcnt[g] = 0; }
            S->gmem[g][S->gcnt[g]++] = m;
        }
        S->ng = ng;
    }

    const int myidx = nidx[b * NNB + i];
    const float* xrow = x + (size_t)myidx * FEAT;
    const float* xb   = x + (size_t)bidx[b] * FEAT;

    // ---- phase 1: 3 feature tiles (16,16,8); j-packed dots accumulate in spdA.
    //      Triangle: warp 0 (i<32) only ever reads its columns <= 35 -> g4 <= 8.
    float nrm = 0.f, cd2 = 0.f;
#pragma unroll
    for (int t = 0; t < 3; t++) {
        const int f0  = (t == 0) ? 0 : (t == 1) ? 16 : 32;
        const int len = (t < 2) ? 16 : 8;
        ull xd[16];
        {
            const ulonglong2* xr = reinterpret_cast<const ulonglong2*>(xrow + f0);
#pragma unroll
            for (int q = 0; q < len / 4; q++) {
                ulonglong2 v = xr[q];
                float f0v, f1v, f2v, f3v;
                unpack2(v.x, f0v, f1v);
                unpack2(v.y, f2v, f3v);
                xd[4*q+0] = pack2(f0v, f0v);
                xd[4*q+1] = pack2(f1v, f1v);
                xd[4*q+2] = pack2(f2v, f2v);
                xd[4*q+3] = pack2(f3v, f3v);
                E->u.p1.sxnT[4*q+0][i] = f0v;
                E->u.p1.sxnT[4*q+1][i] = f1v;
                E->u.p1.sxnT[4*q+2][i] = f2v;
                E->u.p1.sxnT[4*q+3][i] = f3v;
                nrm += f0v*f0v + f1v*f1v;
                nrm += f2v*f2v + f3v*f3v;
            }
        }
        if (i < len) E->u.p1.sxb[i] = xb[f0 + i];
        if (t == 0)  E->sidx[i] = myidx;
        EBAR(idA);

#pragma unroll
        for (int f = 0; f < len; f++) {
            float lo, hi; unpack2(xd[f], lo, hi);
            float d = lo - E->u.p1.sxb[f];
            cd2 += d * d;
        }
        {
            const ulonglong2* colb = reinterpret_cast<const ulonglong2*>(&E->u.p1.sxnT[0][0]);
#pragma unroll 3
            for (int g4 = 0; g4 < 9; g4++) GRAM_G4(g4)
            if (hiwarp) {
#pragma unroll 3
                for (int g4 = 9; g4 < 16; g4++) GRAM_G4(g4)
            }
        }
        EBAR(idA);
    }
    E->snorm[i] = nrm;
    const float cdist = (cd2 > 0.f) ? sqrtf(cd2) : 0.f;
    __syncthreads();

    const float* Yrow = Y + ((size_t)b * NNB + i) * MM;
    const int ng = S->ng;

    for (int g = 0; g < ng; g++) {
        const float inv_ls = 1.0f / S->gls[g];
        const float epg    = S->geps[g];
        const int   nm     = S->gcnt[g];

        // ---- packed Kp row from raw dots; warp-uniform triangle
        ull a2[NNB / 2];
        {
            const float ni = nrm;
#pragma unroll
            for (int p = 0; p < 17; p++) {
                ull dot2 = *reinterpret_cast<const ull*>(&E->spdA[i][2 * p]);
                float d0, d1; unpack2(dot2, d0, d1);
                float dd0 = ni + E->snorm[2*p]   - 2.f * d0;
                float dd1 = ni + E->snorm[2*p+1] - 2.f * d1;
                if (E->sidx[2*p]   == myidx) dd0 = 0.f;
                if (E->sidx[2*p+1] == myidx) dd1 = 0.f;
                dd0 = (dd0 > 0.f) ? sqrtf(dd0) : 0.f;
                dd1 = (dd1 > 0.f) ? sqrtf(dd1) : 0.f;
                float e0 = __expf(-dd0 * inv_ls);
                float e1 = __expf(-dd1 * inv_ls);
                if (2*p   == i) e0 += epg;
                if (2*p+1 == i) e1 += epg;
                a2[p] = pack2(e0, e1);
            }
            if (hiwarp) {
#pragma unroll
                for (int p = 17; p < NNB / 2; p++) {
                    ull dot2 = *reinterpret_cast<const ull*>(&E->spdA[i][2 * p]);
                    float d0, d1; unpack2(dot2, d0, d1);
                    float dd0 = ni + E->snorm[2*p]   - 2.f * d0;
                    float dd1 = ni + E->snorm[2*p+1] - 2.f * d1;
                    if (E->sidx[2*p]   == myidx) dd0 = 0.f;
                    if (E->sidx[2*p+1] == myidx) dd1 = 0.f;
                    dd0 = (dd0 > 0.f) ? sqrtf(dd0) : 0.f;
                    dd1 = (dd1 > 0.f) ? sqrtf(dd1) : 0.f;
                    float e0 = __expf(-dd0 * inv_ls);
                    float e1 = __expf(-dd1 * inv_ls);
                    if (2*p   == i) e0 += epg;
                    if (2*p+1 == i) e1 += epg;
                    a2[p] = pack2(e0, e1);
                }
            }
        }
        const float Kc = __expf(-cdist * inv_ls);

        // ---- packed rhs
        ull rr2[6];
        {
            float rv[RPAD];
#pragma unroll
            for (int r = 0; r < RPAD; r++) rv[r] = 0.f;
#pragma unroll
            for (int r = 0; r < MM; r++)
                if (r < nm) rv[r] = Yrow[S->gmem[g][r]];
#pragma unroll
            for (int r = 0; r < RMAX; r++)
                if (r == nm) rv[r] = Kc;
#pragma unroll
            for (int p = 0; p < 6; p++) rr2[p] = pack2(rv[2*p], rv[2*p+1]);
        }

        float mydv = 0.f;

        // ---- bootstrap: cooperative publish of cols 0/1 into ring buf 0
        {
            float* w0 = E->u.p2.srow[0];
            float lo0, hi0; unpack2(a2[0], lo0, hi0);
            w0[i]      = (i > 0) ? lo0 : 0.f;
            w0[64 + i] = (i > 0) ? hi0 : 0.f;
            if (i == 0) {
                float dv = rsqrtf(lo0);
                mydv = dv;
                w0[160] = dv * dv;
                ulonglong2* wA = reinterpret_cast<ulonglong2*>(w0 + 128);
                wA[0] = make_ulonglong2(rr2[0], rr2[1]);
                wA[1] = make_ulonglong2(rr2[2], rr2[3]);
                wA[2] = make_ulonglong2(rr2[4], rr2[5]);
            }
            if (i == 1) {
                ulonglong2* wB = reinterpret_cast<ulonglong2*>(w0 + 144);
                wB[0] = make_ulonglong2(rr2[0], rr2[1]);
                wB[1] = make_ulonglong2(rr2[2], rr2[3]);
                wB[2] = make_ulonglong2(rr2[4], rr2[5]);
            }
            NBAR_ARRIVE(idA);
        }

        // ---- double-step Cholesky + fused forward solve (rank-2 fold)
#pragma unroll
        for (int n = 0; n < 32; n++) {
            const int K = 2 * n;
            NBAR_SYNC((n & 1) ? idB : idA);
            const float* rbS = E->u.p2.srow[n % 3];
            float*       wbS = E->u.p2.srow[(n + 1) % 3];

            const float dv2a  = rbS[160];
            const float cak1  = rbS[K + 1];
            const float cbk1  = rbS[64 + K + 1];
            const float cc    = cak1 * dv2a;
            const float diagB = __fmaf_rn(-cc, cak1, cbk1);
            const float sdb   = rsqrtf(diagB);
            const float dv2b  = sdb * sdb;
            float aKlo, aKhi; unpack2(a2[n], aKlo, aKhi);
            const float t1  = aKlo * dv2a;
            const float t2  = __fmaf_rn(-t1, cak1, aKhi) * dv2b;
            const float t1p = __fmaf_rn(-t2, cc, t1);   // rank-2 combined multiplier
            const ull nt1p2 = pack2(-t1p, -t1p);
            const ull nt22  = pack2(-t2,  -t2);

            if (n < 31) {
                const int cp2 = n + 1;              // pack holding cols K+2,K+3
                float sA = 0.f, sB = 0.f;
                if (i > K + 1) {
                    ull vA = *reinterpret_cast<const ull*>(rbS + 2 * cp2);
                    ull vB = *reinterpret_cast<const ull*>(rbS + 64 + 2 * cp2);
                    a2[cp2] = fma2(nt1p2, vA, a2[cp2]);
                    a2[cp2] = fma2(nt22,  vB, a2[cp2]);
                    if (i > K + 2) unpack2(a2[cp2], sA, sB);
                }
                wbS[i]      = sA;
                wbS[64 + i] = sB;
                if (i == K + 2) {
                    float dlo, dhi_; unpack2(a2[cp2], dlo, dhi_);
                    float dv = rsqrtf(dlo);
                    mydv = dv;
                    wbS[160] = dv * dv;
                }
            }

            // rhs elimination
            if (i == K + 1) {
                mydv = sdb;
                const ull nt12 = pack2(-t1, -t1);
                const ulonglong2* rA = reinterpret_cast<const ulonglong2*>(rbS + 128);
#pragma unroll
                for (int c = 0; c < 3; c++) {
                    ulonglong2 v = rA[c];
                    rr2[2*c]   = fma2(nt12, v.x, rr2[2*c]);
                    rr2[2*c+1] = fma2(nt12, v.y, rr2[2*c+1]);
                }
            } else if (i > K + 1) {
                const ulonglong2* rA = reinterpret_cast<const ulonglong2*>(rbS + 128);
                const ulonglong2* rB = reinterpret_cast<const ulonglong2*>(rbS + 144);
#pragma unroll
                for (int c = 0; c < 3; c++) {
                    ulonglong2 vA = rA[c], vB = rB[c];
                    rr2[2*c]   = fma2(nt1p2, vA.x, rr2[2*c]);
                    rr2[2*c]   = fma2(nt22,  vB.x, rr2[2*c]);
                    rr2[2*c+1] = fma2(nt1p2, vA.y, rr2[2*c+1]);
                    rr2[2*c+1] = fma2(nt22,  vB.y, rr2[2*c+1]);
                }
            }

            if (n < 31) {
                if (i == K + 2) {
                    ulonglong2* wA = reinterpret_cast<ulonglong2*>(wbS + 128);
                    wA[0] = make_ulonglong2(rr2[0], rr2[1]);
                    wA[1] = make_ulonglong2(rr2[2], rr2[3]);
                    wA[2] = make_ulonglong2(rr2[4], rr2[5]);
                }
                if (i == K + 3) {
                    ulonglong2* wB = reinterpret_cast<ulonglong2*>(wbS + 144);
                    wB[0] = make_ulonglong2(rr2[0], rr2[1]);
                    wB[1] = make_ulonglong2(rr2[2], rr2[3]);
                    wB[2] = make_ulonglong2(rr2[4], rr2[5]);
                }
                NBAR_ARRIVE((n & 1) ? idA : idB);

                // ---- tail: remaining packs; warp-uniform triangle split
                if (i > K + 1) {
                    const int pt0 = n + 2;           // first tail pack
                    if (pt0 & 1) {
                        if (pt0 <= 16) {
                            ull vA = *reinterpret_cast<const ull*>(rbS + 2 * pt0);
                            ull vB = *reinterpret_cast<const ull*>(rbS + 64 + 2 * pt0);
                            a2[pt0] = fma2(nt1p2, vA, a2[pt0]);
                            a2[pt0] = fma2(nt22,  vB, a2[pt0]);
                        } else if (pt0 < 32 && hiwarp) {
                            ull vA = *reinterpret_cast<const ull*>(rbS + 2 * pt0);
                            ull vB = *reinterpret_cast<const ull*>(rbS + 64 + 2 * pt0);
                            a2[pt0] = fma2(nt1p2, vA, a2[pt0]);
                            a2[pt0] = fma2(nt22,  vB, a2[pt0]);
                        }
                    }
                    const int c0 = (pt0 + 1) >> 1;
#pragma unroll
                    for (int c = c0; c < 8; c++) {
                        ulonglong2 vA2 = *reinterpret_cast<const ulonglong2*>(rbS + 4 * c);
                        ulonglong2 vB2 = *reinterpret_cast<const ulonglong2*>(rbS + 64 + 4 * c);
                        a2[2*c]   = fma2(nt1p2, vA2.x, a2[2*c]);
                        a2[2*c]   = fma2(nt22,  vB2.x, a2[2*c]);
                        a2[2*c+1] = fma2(nt1p2, vA2.y, a2[2*c+1]);
                        a2[2*c+1] = fma2(nt22,  vB2.y, a2[2*c+1]);
                    }
                    if (hiwarp) {
                        const int ch0 = (c0 > 8) ? c0 : 8;
#pragma unroll
                        for (int c = ch0; c < 16; c++) {
                            ulonglong2 vA2 = *reinterpret_cast<const ulonglong2*>(rbS + 4 * c);
                            ulonglong2 vB2 = *reinterpret_cast<const ulonglong2*>(rbS + 64 + 4 * c);
                            a2[2*c]   = fma2(nt1p2, vA2.x, a2[2*c]);
                            a2[2*c]   = fma2(nt22,  vB2.x, a2[2*c]);
                            a2[2*c+1] = fma2(nt1p2, vA2.y, a2[2*c+1]);
                            a2[2*c+1] = fma2(nt22,  vB2.y, a2[2*c+1]);
                        }
                    }
                }
            }
        }

        // ---- zs = D^{-1/2} L^{-1} rhs; outputs are inner products
        {
            ull mv2 = pack2(mydv, mydv);
#pragma unroll
            for (int p = 0; p < 6; p++) rr2[p] = mul2(rr2[p], mv2);
        }
        float z[RPAD];
#pragma unroll
        for (int p = 0; p < 6; p++) unpack2(rr2[p], z[2*p], z[2*p+1]);

        float zKc = 0.f;
#pragma unroll
        for (int r = 0; r < RMAX; r++)
            if (r == nm) zKc = z[r];

        float pm[MM], sg[MM];
#pragma unroll
        for (int r = 0; r < MM; r++) { pm[r] = z[r] * zKc; sg[r] = z[r] * z[r]; }
        float vv = zKc * zKc;

#pragma unroll
        for (int off = 16; off > 0; off >>= 1) {
#pragma unroll
            for (int r = 0; r < MM; r++) {
                pm[r] += __shfl_xor_sync(0xffffffffu, pm[r], off);
                sg[r] += __shfl_xor_sync(0xffffffffu, sg[r], off);
            }
            vv += __shfl_xor_sync(0xffffffffu, vv, off);
        }
        {
            const int w = (tid >> 5) & 1, lane = tid & 31;
            if (lane == 0) {
#pragma unroll
                for (int r = 0; r < MM; r++) {
                    E->red[w][r]      = pm[r];
                    E->red[w][MM + r] = sg[r];
                }
                E->red[w][2 * MM] = vv;
            }
        }
        EBAR(idA);
        if (i == 0) {
            float var = 1.0f - (E->red[0][2*MM] + E->red[1][2*MM]);
            for (int r = 0; r < nm; r++) {
                int m = S->gmem[g][r];
                out[b * MM + m]              = E->red[0][r] + E->red[1][r];
                out[BATCH * MM + b * MM + m] = var;
                g_sig_partial[m * BATCH + b] = E->red[0][MM+r] + E->red[1][MM+r];
            }
        }
        EBAR(idA);
    }

    // ---- last-block sigma reduction (deterministic fixed-order sum)
    __threadfence();
    __syncthreads();
    if (tid == 0) S->ticket = atomicAdd(&g_done, 1u);
    __syncthreads();
    if (S->ticket == gridDim.x - 1) {
        __threadfence();
        const int lane = tid & 31, w = tid >> 5;
        for (int m = 0; m < MM; m++) {
            float s = 0.f;
            for (int t = tid; t < BATCH; t += 128)
                s += g_sig_partial[m * BATCH + t];
#pragma unroll
            for (int off = 16; off > 0; off >>= 1)
                s += __shfl_down_sync(0xffffffffu, s, off);
            if (lane == 0) S->sred[w] = s;
            __syncthreads();
            if (tid == 0) {
                float tot = S->sred[0] + S->sred[1] + S->sred[2] + S->sred[3];
                out[2 * BATCH * MM + m] = tot / (float)(BATCH * NNB);
            }
            __syncthreads();
        }
        if (tid == 0) g_done = 0;
    }
}

extern "C" void kernel_launch(void* const* d_in, const int* in_sizes, int n_in,
                              void* d_out, int out_size)
{
    const float* x    = (const float*)d_in[0];
    const float* ls   = (const float*)d_in[1];
    const float* eps  = (const float*)d_in[2];
    const int*   bidx = (const int*)d_in[3];
    const int*   nidx = (const int*)d_in[4];
    const float* Y    = (const float*)d_in[5];
    float* out = (float*)d_out;

    cudaFuncSetAttribute(muygps_main, cudaFuncAttributeMaxDynamicSharedMemorySize,
                         (int)sizeof(BlockSmem));
    muygps_main<<<BATCH / 2, 128, sizeof(BlockSmem)>>>(x, ls, eps, bidx, nidx, Y, out);
}

// round 17
// speedup vs baseline: 1.2571x; 1.0247x over previous
#include <cuda_runtime.h>

#define BATCH 2048
#define NNB   64
#define MM    10
#define FEAT  40
#define RMAX  (MM + 1)
#define RPAD  12
#define PDS   66

typedef unsigned long long ull;

__device__ float g_sig_partial[MM * BATCH];
__device__ unsigned int g_done = 0;

#define EBAR(id)        asm volatile("bar.sync %0, 64;"    :: "r"(id) : "memory")
#define NBAR_SYNC(id)   asm volatile("bar.sync %0, 128;"   :: "r"(id) : "memory")
#define NBAR_ARRIVE(id) asm volatile("bar.arrive %0, 128;" :: "r"(id) : "memory")

__device__ __forceinline__ ull pack2(float lo, float hi) {
    ull r; asm("mov.b64 %0, {%1, %2};" : "=l"(r) : "f"(lo), "f"(hi)); return r;
}
__device__ __forceinline__ void unpack2(ull v, float& lo, float& hi) {
    asm("mov.b64 {%0, %1}, %2;" : "=f"(lo), "=f"(hi) : "l"(v));
}
__device__ __forceinline__ ull fma2(ull a, ull b, ull c) {
    ull r; asm("fma.rn.f32x2 %0, %1, %2, %3;" : "=l"(r) : "l"(a), "l"(b), "l"(c)); return r;
}
__device__ __forceinline__ ull add2(ull a, ull b) {
    ull r; asm("add.rn.f32x2 %0, %1, %2;" : "=l"(r) : "l"(a), "l"(b)); return r;
}
__device__ __forceinline__ ull mul2(ull a, ull b) {
    ull r; asm("mul.rn.f32x2 %0, %1, %2;" : "=l"(r) : "l"(a), "l"(b)); return r;
}

struct __align__(16) ElemSmem {
    float spdA[NNB][PDS];                // raw pairwise dots
    union {
        struct {                          // phase 1: transposed feature staging
            float sxnT[16][NNB];
            float sxb[16];
        } p1;
        struct {                          // phase 2: 3-deep publish ring
            float srow[3][176];           // [0..63] colA, [64..127] colB,
                                          // [128..139] rhsA, [144..155] rhsB, [160] dv2a
        } p2;
    } u;
    float snorm[NNB];
    int   sidx[NNB];
    float red[2][2 * MM + 2];             // pm[0..9], sg[10..19], vv[20]
};

struct BlockSmem {
    ElemSmem e[2];
    float gls[MM], geps[MM];
    int   gcnt[MM];
    int   gmem[MM][MM];
    int   ng;
    unsigned int ticket;
    float sred[4];
};

// one g4 group of the j-packed Gram update
#define GRAM_G4(g4)                                                              \
    {                                                                            \
        ull acc0 = 0ull, acc1 = 0ull;                                            \
        _Pragma("unroll")                                                        \
        for (int f = 0; f < len; f++) {                                          \
            ulonglong2 v = colb[16 * f + (g4)];                                  \
            acc0 = fma2(xd[f], v.x, acc0);                                       \
            acc1 = fma2(xd[f], v.y, acc1);                                       \
        }                                                                        \
        ull* dst = reinterpret_cast<ull*>(&E->spdA[i][4 * (g4)]);                \
        if (t == 0) { dst[0] = acc0; dst[1] = acc1; }                            \
        else        { dst[0] = add2(dst[0], acc0); dst[1] = add2(dst[1], acc1); }\
    }

// packed Kp-build for one pack p
#define KP_PACK(p)                                                               \
    {                                                                            \
        ull dot2 = *reinterpret_cast<const ull*>(&E->spdA[i][2 * (p)]);          \
        ull n2   = *reinterpret_cast<const ull*>(&E->snorm[2 * (p)]);            \
        ull dd2  = fma2(nm2, dot2, add2(ni2, n2));                               \
        float dd0, dd1; unpack2(dd2, dd0, dd1);                                  \
        int2 si = *reinterpret_cast<const int2*>(&E->sidx[2 * (p)]);             \
        if (si.x == myidx) dd0 = 0.f;                                            \
        if (si.y == myidx) dd1 = 0.f;                                            \
        dd0 = (dd0 > 0.f) ? sqrtf(dd0) : 0.f;                                    \
        dd1 = (dd1 > 0.f) ? sqrtf(dd1) : 0.f;                                    \
        float e0 = __expf(-dd0 * inv_ls);                                        \
        float e1 = __expf(-dd1 * inv_ls);                                        \
        if (2 * (p)     == i) e0 += epg;                                         \
        if (2 * (p) + 1 == i) e1 += epg;                                         \
        a2[p] = pack2(e0, e1);                                                   \
    }

__global__ void __launch_bounds__(128, 5)
muygps_main(const float* __restrict__ x,
            const float* __restrict__ ls,
            const float* __restrict__ eps,
            const int*   __restrict__ bidx,
            const int*   __restrict__ nidx,
            const float* __restrict__ Y,
            float*       __restrict__ out)
{
    extern __shared__ char smem_raw[];
    BlockSmem* S = reinterpret_cast<BlockSmem*>(smem_raw);
    const int tid = threadIdx.x;
    const int e   = tid >> 6;
    const int i   = tid & 63;
    const int idA = 1 + 2 * e;
    const int idB = 2 + 2 * e;
    const int b   = blockIdx.x * 2 + e;
    ElemSmem* E = &S->e[e];
    const bool hiwarp = (i & 32) != 0;   // warp-uniform triangle predicate

    if (tid == 0) {
        int ng = 0;
        for (int m = 0; m < MM; m++) {
            float lm = ls[m], em = eps[m];
            int g = -1;
            for (int q = 0; q < ng; q++)
                if (S->gls[q] == lm && S->geps[q] == em) { g = q; break; }
            if (g < 0) { g = ng++; S->gls[g] = lm; S->geps[g] = em; S->gcnt[g] = 0; }
            S->gmem[g][S->gcnt[g]++] = m;
        }
        S->ng = ng;
    }

    const int myidx = nidx[b * NNB + i];
    const float* xrow = x + (size_t)myidx * FEAT;
    const float* xb   = x + (size_t)bidx[b] * FEAT;

    // ---- phase 1: 3 feature tiles (16,16,8); j-packed dots accumulate in spdA.
    //      Triangle: warp 0 (i<32) only ever reads its columns <= 35 -> g4 <= 8.
    float nrm = 0.f, cd2 = 0.f;
#pragma unroll
    for (int t = 0; t < 3; t++) {
        const int f0  = (t == 0) ? 0 : (t == 1) ? 16 : 32;
        const int len = (t < 2) ? 16 : 8;
        ull xd[16];
        {
            const ulonglong2* xr = reinterpret_cast<const ulonglong2*>(xrow + f0);
#pragma unroll
            for (int q = 0; q < len / 4; q++) {
                ulonglong2 v = xr[q];
                float f0v, f1v, f2v, f3v;
                unpack2(v.x, f0v, f1v);
                unpack2(v.y, f2v, f3v);
                xd[4*q+0] = pack2(f0v, f0v);
                xd[4*q+1] = pack2(f1v, f1v);
                xd[4*q+2] = pack2(f2v, f2v);
                xd[4*q+3] = pack2(f3v, f3v);
                E->u.p1.sxnT[4*q+0][i] = f0v;
                E->u.p1.sxnT[4*q+1][i] = f1v;
                E->u.p1.sxnT[4*q+2][i] = f2v;
                E->u.p1.sxnT[4*q+3][i] = f3v;
                nrm += f0v*f0v + f1v*f1v;
                nrm += f2v*f2v + f3v*f3v;
            }
        }
        if (i < len) E->u.p1.sxb[i] = xb[f0 + i];
        if (t == 0)  E->sidx[i] = myidx;
        EBAR(idA);

#pragma unroll
        for (int f = 0; f < len; f++) {
            float lo, hi; unpack2(xd[f], lo, hi);
            float d = lo - E->u.p1.sxb[f];
            cd2 += d * d;
        }
        {
            const ulonglong2* colb = reinterpret_cast<const ulonglong2*>(&E->u.p1.sxnT[0][0]);
#pragma unroll 3
            for (int g4 = 0; g4 < 9; g4++) GRAM_G4(g4)
            if (hiwarp) {
#pragma unroll 3
                for (int g4 = 9; g4 < 16; g4++) GRAM_G4(g4)
            }
        }
        EBAR(idA);
    }
    E->snorm[i] = nrm;
    const float cdist = (cd2 > 0.f) ? sqrtf(cd2) : 0.f;
    __syncthreads();

    const float* Yrow = Y + ((size_t)b * NNB + i) * MM;
    const int ng = S->ng;

    for (int g = 0; g < ng; g++) {
        const float inv_ls = 1.0f / S->gls[g];
        const float epg    = S->geps[g];
        const int   nm     = S->gcnt[g];

        // ---- packed Kp row from raw dots; warp-uniform triangle
        ull a2[NNB / 2];
        {
            const ull ni2 = pack2(nrm, nrm);
            const ull nm2 = pack2(-2.f, -2.f);
#pragma unroll
            for (int p = 0; p < 17; p++) KP_PACK(p)
            if (hiwarp) {
#pragma unroll
                for (int p = 17; p < NNB / 2; p++) KP_PACK(p)
            }
        }
        const float Kc = __expf(-cdist * inv_ls);

        // ---- packed rhs
        ull rr2[6];
        {
            float rv[RPAD];
#pragma unroll
            for (int r = 0; r < RPAD; r++) rv[r] = 0.f;
#pragma unroll
            for (int r = 0; r < MM; r++)
                if (r < nm) rv[r] = Yrow[S->gmem[g][r]];
#pragma unroll
            for (int r = 0; r < RMAX; r++)
                if (r == nm) rv[r] = Kc;
#pragma unroll
            for (int p = 0; p < 6; p++) rr2[p] = pack2(rv[2*p], rv[2*p+1]);
        }

        float mydv = 0.f;

        // ---- bootstrap: cooperative publish of cols 0/1 into ring buf 0
        {
            float* w0 = E->u.p2.srow[0];
            float lo0, hi0; unpack2(a2[0], lo0, hi0);
            w0[i]      = (i > 0) ? lo0 : 0.f;
            w0[64 + i] = (i > 0) ? hi0 : 0.f;
            if (i == 0) {
                float dv = rsqrtf(lo0);
                mydv = dv;
                w0[160] = dv * dv;
                ulonglong2* wA = reinterpret_cast<ulonglong2*>(w0 + 128);
                wA[0] = make_ulonglong2(rr2[0], rr2[1]);
                wA[1] = make_ulonglong2(rr2[2], rr2[3]);
                wA[2] = make_ulonglong2(rr2[4], rr2[5]);
            }
            if (i == 1) {
                ulonglong2* wB = reinterpret_cast<ulonglong2*>(w0 + 144);
                wB[0] = make_ulonglong2(rr2[0], rr2[1]);
                wB[1] = make_ulonglong2(rr2[2], rr2[3]);
                wB[2] = make_ulonglong2(rr2[4], rr2[5]);
            }
            NBAR_ARRIVE(idA);
        }

        // ---- double-step Cholesky + fused forward solve (rank-2 fold).
        //      Warp-uniform skip: warp 0 is fully idle for n >= 16; barrier ops
        //      stay OUTSIDE the skip and textually unique (warp-aggregated bar).
#pragma unroll
        for (int n = 0; n < 32; n++) {
            const int K = 2 * n;
            NBAR_SYNC((n & 1) ? idB : idA);
            const float* rbS = E->u.p2.srow[n % 3];
            float*       wbS = E->u.p2.srow[(n + 1) % 3];

            const bool wactive = hiwarp || (n < 16);   // warp-uniform
            ull nt1p2 = 0ull, nt22 = 0ull;

            if (wactive) {
                const float dv2a  = rbS[160];
                const float cak1  = rbS[K + 1];
                const float cbk1  = rbS[64 + K + 1];
                const float cc    = cak1 * dv2a;
                const float diagB = __fmaf_rn(-cc, cak1, cbk1);
                const float sdb   = rsqrtf(diagB);
                const float dv2b  = sdb * sdb;
                float aKlo, aKhi; unpack2(a2[n], aKlo, aKhi);
                const float t1  = aKlo * dv2a;
                const float t2  = __fmaf_rn(-t1, cak1, aKhi) * dv2b;
                const float t1p = __fmaf_rn(-t2, cc, t1);
                nt1p2 = pack2(-t1p, -t1p);
                nt22  = pack2(-t2,  -t2);

                if (n < 31) {
                    const int cp2 = n + 1;              // pack holding cols K+2,K+3
                    float sA = 0.f, sB = 0.f;
                    if (i > K + 1) {
                        ull vA = *reinterpret_cast<const ull*>(rbS + 2 * cp2);
                        ull vB = *reinterpret_cast<const ull*>(rbS + 64 + 2 * cp2);
                        a2[cp2] = fma2(nt1p2, vA, a2[cp2]);
                        a2[cp2] = fma2(nt22,  vB, a2[cp2]);
                        if (i > K + 2) unpack2(a2[cp2], sA, sB);
                    }
                    wbS[i]      = sA;
                    wbS[64 + i] = sB;
                    if (i == K + 2) {
                        float dlo, dhi_; unpack2(a2[cp2], dlo, dhi_);
                        float dv = rsqrtf(dlo);
                        mydv = dv;
                        wbS[160] = dv * dv;
                    }
                }

                // rhs elimination
                if (i == K + 1) {
                    mydv = sdb;
                    const ull nt12 = pack2(-t1, -t1);
                    const ulonglong2* rA = reinterpret_cast<const ulonglong2*>(rbS + 128);
#pragma unroll
                    for (int c = 0; c < 3; c++) {
                        ulonglong2 v = rA[c];
                        rr2[2*c]   = fma2(nt12, v.x, rr2[2*c]);
                        rr2[2*c+1] = fma2(nt12, v.y, rr2[2*c+1]);
                    }
                } else if (i > K + 1) {
                    const ulonglong2* rA = reinterpret_cast<const ulonglong2*>(rbS + 128);
                    const ulonglong2* rB = reinterpret_cast<const ulonglong2*>(rbS + 144);
#pragma unroll
                    for (int c = 0; c < 3; c++) {
                        ulonglong2 vA = rA[c], vB = rB[c];
                        rr2[2*c]   = fma2(nt1p2, vA.x, rr2[2*c]);
                        rr2[2*c]   = fma2(nt22,  vB.x, rr2[2*c]);
                        rr2[2*c+1] = fma2(nt1p2, vA.y, rr2[2*c+1]);
                        rr2[2*c+1] = fma2(nt22,  vB.y, rr2[2*c+1]);
                    }
                }

                if (n < 31) {
                    if (i == K + 2) {
                        ulonglong2* wA = reinterpret_cast<ulonglong2*>(wbS + 128);
                        wA[0] = make_ulonglong2(rr2[0], rr2[1]);
                        wA[1] = make_ulonglong2(rr2[2], rr2[3]);
                        wA[2] = make_ulonglong2(rr2[4], rr2[5]);
                    }
                    if (i == K + 3) {
                        ulonglong2* wB = reinterpret_cast<ulonglong2*>(wbS + 144);
                        wB[0] = make_ulonglong2(rr2[0], rr2[1]);
                        wB[1] = make_ulonglong2(rr2[2], rr2[3]);
                        wB[2] = make_ulonglong2(rr2[4], rr2[5]);
                    }
                }
            }

            if (n < 31) NBAR_ARRIVE((n & 1) ? idA : idB);   // single uniform site

            if (wactive && n < 31) {
                // ---- tail: remaining packs; warp-uniform triangle split
                if (i > K + 1) {
                    const int pt0 = n + 2;           // first tail pack
                    if (pt0 & 1) {
                        if (pt0 <= 16) {
                            ull vA = *reinterpret_cast<const ull*>(rbS + 2 * pt0);
                            ull vB = *reinterpret_cast<const ull*>(rbS + 64 + 2 * pt0);
                            a2[pt0] = fma2(nt1p2, vA, a2[pt0]);
                            a2[pt0] = fma2(nt22,  vB, a2[pt0]);
                        } else if (pt0 < 32 && hiwarp) {
                            ull vA = *reinterpret_cast<const ull*>(rbS + 2 * pt0);
                            ull vB = *reinterpret_cast<const ull*>(rbS + 64 + 2 * pt0);
                            a2[pt0] = fma2(nt1p2, vA, a2[pt0]);
                            a2[pt0] = fma2(nt22,  vB, a2[pt0]);
                        }
                    }
                    const int c0 = (pt0 + 1) >> 1;
#pragma unroll
                    for (int c = c0; c < 8; c++) {
                        ulonglong2 vA2 = *reinterpret_cast<const ulonglong2*>(rbS + 4 * c);
                        ulonglong2 vB2 = *reinterpret_cast<const ulonglong2*>(rbS + 64 + 4 * c);
                        a2[2*c]   = fma2(nt1p2, vA2.x, a2[2*c]);
                        a2[2*c]   = fma2(nt22,  vB2.x, a2[2*c]);
                        a2[2*c+1] = fma2(nt1p2, vA2.y, a2[2*c+1]);
                        a2[2*c+1] = fma2(nt22,  vB2.y, a2[2*c+1]);
                    }
                    if (hiwarp) {
                        const int ch0 = (c0 > 8) ? c0 : 8;
#pragma unroll
                        for (int c = ch0; c < 16; c++) {
                            ulonglong2 vA2 = *reinterpret_cast<const ulonglong2*>(rbS + 4 * c);
                            ulonglong2 vB2 = *reinterpret_cast<const ulonglong2*>(rbS + 64 + 4 * c);
                            a2[2*c]   = fma2(nt1p2, vA2.x, a2[2*c]);
                            a2[2*c]   = fma2(nt22,  vB2.x, a2[2*c]);
                            a2[2*c+1] = fma2(nt1p2, vA2.y, a2[2*c+1]);
                            a2[2*c+1] = fma2(nt22,  vB2.y, a2[2*c+1]);
                        }
                    }
                }
            }
        }

        // ---- zs = D^{-1/2} L^{-1} rhs; packed inner-product epilogue
        {
            ull mv2 = pack2(mydv, mydv);
#pragma unroll
            for (int p = 0; p < 6; p++) rr2[p] = mul2(rr2[p], mv2);
        }
        float zKc = 0.f;
#pragma unroll
        for (int r = 0; r < RMAX; r++)
            if (r == nm) {
                float lo, hi; unpack2(rr2[r >> 1], lo, hi);
                zKc = (r & 1) ? hi : lo;
            }
        ull zkc2 = pack2(zKc, zKc);
        ull pm2[5], sg2[5];
#pragma unroll
        for (int p = 0; p < 5; p++) {
            pm2[p] = mul2(rr2[p], zkc2);
            sg2[p] = mul2(rr2[p], rr2[p]);
        }
        float vv = zKc * zKc;

#pragma unroll
        for (int off = 16; off > 0; off >>= 1) {
#pragma unroll
            for (int p = 0; p < 5; p++) {
                pm2[p] = add2(pm2[p], __shfl_xor_sync(0xffffffffu, pm2[p], off));
                sg2[p] = add2(sg2[p], __shfl_xor_sync(0xffffffffu, sg2[p], off));
            }
            vv += __shfl_xor_sync(0xffffffffu, vv, off);
        }
        {
            const int w = (tid >> 5) & 1, lane = tid & 31;
            if (lane == 0) {
#pragma unroll
                for (int p = 0; p < 5; p++) {
                    *reinterpret_cast<ull*>(&E->red[w][2 * p])      = pm2[p];
                    *reinterpret_cast<ull*>(&E->red[w][MM + 2 * p]) = sg2[p];
                }
                E->red[w][2 * MM] = vv;
            }
        }
        EBAR(idA);
        if (i == 0) {
            float var = 1.0f - (E->red[0][2*MM] + E->red[1][2*MM]);
            for (int r = 0; r < nm; r++) {
                int m = S->gmem[g][r];
                out[b * MM + m]              = E->red[0][r] + E->red[1][r];
                out[BATCH * MM + b * MM + m] = var;
                g_sig_partial[m * BATCH + b] = E->red[0][MM+r] + E->red[1][MM+r];
            }
        }
        EBAR(idA);
    }

    // ---- last-block sigma reduction (deterministic fixed-order sum)
    __threadfence();
    __syncthreads();
    if (tid == 0) S->ticket = atomicAdd(&g_done, 1u);
    __syncthreads();
    if (S->ticket == gridDim.x - 1) {
        __threadfence();
        const int lane = tid & 31, w = tid >> 5;
        for (int m = 0; m < MM; m++) {
            float s = 0.f;
            for (int t = tid; t < BATCH; t += 128)
                s += g_sig_partial[m * BATCH + t];
#pragma unroll
            for (int off = 16; off > 0; off >>= 1)
                s += __shfl_down_sync(0xffffffffu, s, off);
            if (lane == 0) S->sred[w] = s;
            __syncthreads();
            if (tid == 0) {
                float tot = S->sred[0] + S->sred[1] + S->sred[2] + S->sred[3];
                out[2 * BATCH * MM + m] = tot / (float)(BATCH * NNB);
            }
            __syncthreads();
        }
        if (tid == 0) g_done = 0;
    }
}

extern "C" void kernel_launch(void* const* d_in, const int* in_sizes, int n_in,
                              void* d_out, int out_size)
{
    const float* x    = (const float*)d_in[0];
    const float* ls   = (const float*)d_in[1];
    const float* eps  = (const float*)d_in[2];
    const int*   bidx = (const int*)d_in[3];
    const int*   nidx = (const int*)d_in[4];
    const float* Y    = (const float*)d_in[5];
    float* out = (float*)d_out;

    cudaFuncSetAttribute(muygps_main, cudaFuncAttributeMaxDynamicSharedMemorySize,
                         (int)sizeof(BlockSmem));
    muygps_main<<<BATCH / 2, 128, sizeof(BlockSmem)>>>(x, ls, eps, bidx, nidx, Y, out);
}